// round 3
// baseline (speedup 1.0000x reference)
#include <cuda_runtime.h>
#include <cstdint>

#define NB   2048
#define INS  512
#define SEQL 128
#define NH   12
#define NOUT 3
#define BPB  8    // batches per block in pre_kernel (1 warp per batch)
#define SCH  32   // s-chunk per block

// scratch (allocation-free contract: __device__ globals)
__device__ float g_pre[(size_t)SEQL * NB * NH];   // [s][b][h]  ~12.6 MB
__device__ float g_hbwd[NB * NH];

__device__ __forceinline__ unsigned long long fma2(unsigned long long a,
                                                   unsigned long long b,
                                                   unsigned long long c) {
    unsigned long long d;
    asm("fma.rn.f32x2 %0, %1, %2, %3;" : "=l"(d) : "l"(a), "l"(b), "l"(c));
    return d;
}
__device__ __forceinline__ unsigned long long pk2(float f) {
    unsigned long long u;
    asm("mov.b64 %0, {%1, %1};" : "=l"(u) : "f"(f));
    return u;
}
__device__ __forceinline__ float ftanh(float x) {
    float e = __expf(2.0f * x);
    return 1.0f - __fdividef(2.0f, e + 1.0f);
}

// ---------------------------------------------------------------------------
// Kernel 1: pre[s,b,h] = sum_i emb[x[b,i], s] * w_ih_f[h,i]
// grid (NB/BPB, SEQL/SCH); block 256 = 8 warps = 8 batches; lane owns s0+lane.
// smem: emb slice [512 v][32 s] (64KB, 8x batch reuse -> L2 traffic /8),
//       weight pairs (w[2k],w[2k+1]) (24KB), x rows (16KB).
// Gather e = LDS.32 (idx uniform per warp, lanes consecutive s: conflict-free).
// 6 fma.rn.f32x2 per i per lane.
// ---------------------------------------------------------------------------
extern "C" __global__ void __launch_bounds__(256)
pre_kernel(const int* __restrict__ x, const float* __restrict__ emb,
           const float* __restrict__ wih) {
    extern __shared__ char dynsmem[];
    float*  tile = (float*)dynsmem;                         // [512*SCH] 64 KB
    float2* w2   = (float2*)(dynsmem + INS * SCH * 4);      // [512*6]   24 KB
    int*    xs   = (int*)(dynsmem + INS * SCH * 4 + INS * 6 * 8); // [BPB*512] 16 KB

    const int tid = threadIdx.x;
    const int b0 = blockIdx.x * BPB;
    const int s0 = blockIdx.y * SCH;

    // stage emb slice: tile[v*SCH + s] = emb[v*SEQL + s0 + s]; coalesced both ways
    for (int t = tid; t < INS * SCH; t += 256) {
        int v = t >> 5, s = t & (SCH - 1);
        tile[t] = emb[v * SEQL + s0 + s];
    }
    // stage weight pairs: w2[i*6+k] = (w[2k,i], w[2k+1,i])
    for (int t = tid; t < INS * 6; t += 256) {
        int i = t & (INS - 1), k = t >> 9;
        w2[i * 6 + k] = make_float2(wih[(2 * k) * INS + i],
                                    wih[(2 * k + 1) * INS + i]);
    }
    for (int t = tid; t < BPB * INS; t += 256)
        xs[t] = x[(size_t)b0 * INS + t];
    __syncthreads();

    const int warp = tid >> 5;
    const int lane = tid & 31;
    const int b = b0 + warp;
    const int* xrow = xs + warp * INS;

    unsigned long long acc[6];
#pragma unroll
    for (int k = 0; k < 6; k++) acc[k] = 0ull;

#pragma unroll 2
    for (int i0 = 0; i0 < INS; i0 += 4) {
        int4 q = *(const int4*)(xrow + i0);   // broadcast LDS.128, 4 indices
#pragma unroll
        for (int u = 0; u < 4; u++) {
            int idx = (u == 0) ? q.x : (u == 1) ? q.y : (u == 2) ? q.z : q.w;
            float e = tile[idx * SCH + lane];            // conflict-free LDS.32
            unsigned long long ep = pk2(e);
            const ulonglong2* wv = (const ulonglong2*)(w2 + (size_t)(i0 + u) * 6);
            ulonglong2 wA = wv[0], wB = wv[1], wC = wv[2]; // 3 broadcast LDS.128
            acc[0] = fma2(ep, wA.x, acc[0]);
            acc[1] = fma2(ep, wA.y, acc[1]);
            acc[2] = fma2(ep, wB.x, acc[2]);
            acc[3] = fma2(ep, wB.y, acc[3]);
            acc[4] = fma2(ep, wC.x, acc[4]);
            acc[5] = fma2(ep, wC.y, acc[5]);
        }
    }

    // acc[k] = (pre[s,b,2k], pre[s,b,2k+1]); 12 contiguous floats at [s][b][:]
    const int s = s0 + lane;
    ulonglong2* d = (ulonglong2*)(g_pre + ((size_t)s * NB + b) * NH);
    ulonglong2 v0, v1, v2;
    v0.x = acc[0]; v0.y = acc[1];
    v1.x = acc[2]; v1.y = acc[3];
    v2.x = acc[4]; v2.y = acc[5];
    d[0] = v0; d[1] = v1; d[2] = v2;
}

// ---------------------------------------------------------------------------
// Kernel 2: h_bwd[b,h] = tanh( sum_i emb[x[b,i],127]*w_ih_r[h,i] + b_ih_r + b_hh_r )
// Warp per batch; 16-deep prefetch of idx then e (MLP=16) kills the dependent-
// load chain that cost 20.5us in R2.
// ---------------------------------------------------------------------------
extern "C" __global__ void __launch_bounds__(256)
bwd_kernel(const int* __restrict__ x, const float* __restrict__ emb,
           const float* __restrict__ wir, const float* __restrict__ bir,
           const float* __restrict__ bhr) {
    __shared__ float ws[NH * INS];   // 24 KB
    const int tid = threadIdx.x;
    for (int t = tid; t < NH * INS; t += 256) ws[t] = wir[t];
    __syncthreads();

    const int warp = tid >> 5, lane = tid & 31;
    const int b = blockIdx.x * 8 + warp;

    int idxv[16];
#pragma unroll
    for (int j = 0; j < 16; j++)
        idxv[j] = x[(size_t)b * INS + lane + 32 * j];   // 16 coalesced LDG in flight
    float ev[16];
#pragma unroll
    for (int j = 0; j < 16; j++)
        ev[j] = emb[(size_t)idxv[j] * SEQL + (SEQL - 1)]; // 16 scattered LDG in flight

    float p[NH];
#pragma unroll
    for (int h = 0; h < NH; h++) p[h] = 0.f;
#pragma unroll
    for (int j = 0; j < 16; j++) {
        const int i = lane + 32 * j;
#pragma unroll
        for (int h = 0; h < NH; h++) p[h] = fmaf(ev[j], ws[h * INS + i], p[h]);
    }

    // butterfly reduce: every lane ends with full sums
#pragma unroll
    for (int h = 0; h < NH; h++) {
        float v = p[h];
#pragma unroll
        for (int o = 16; o; o >>= 1) v += __shfl_xor_sync(0xffffffffu, v, o);
        p[h] = v;
    }
    if (lane == 0) {
        float r[NH];
#pragma unroll
        for (int h = 0; h < NH; h++) r[h] = ftanh(p[h] + bir[h] + bhr[h]);
        float4* d = (float4*)(g_hbwd + (size_t)b * NH);
        d[0] = make_float4(r[0], r[1], r[2], r[3]);
        d[1] = make_float4(r[4], r[5], r[6], r[7]);
        d[2] = make_float4(r[8], r[9], r[10], r[11]);
    }
}

// ---------------------------------------------------------------------------
// Kernel 3: forward scan over 128 steps + fused FC epilogue.
// 16 lanes per batch (h = lane&15), shfl width 16. Fast tanh via __expf.
// ---------------------------------------------------------------------------
extern "C" __global__ void __launch_bounds__(256)
scan_kernel(const float* __restrict__ whh, const float* __restrict__ bih,
            const float* __restrict__ bhh, const float* __restrict__ fcw,
            const float* __restrict__ fcb, float* __restrict__ out) {
    const int tid = threadIdx.x;
    const int b = blockIdx.x * 16 + (tid >> 4);
    const int hl = tid & 15;
    const int hc = hl < NH ? hl : 0;

    float wrow[NH];
#pragma unroll
    for (int j = 0; j < NH; j++) wrow[j] = whh[hc * NH + j];
    const float bias = bih[hc] + bhh[hc];

    const float* ps = g_pre + (size_t)b * NH + hc;
    float h = 0.f;
    float pnext = ps[0];

    for (int s = 0; s < SEQL; s++) {
        float p = pnext;
        if (s + 1 < SEQL) pnext = ps[(size_t)(s + 1) * NB * NH];
        float v[NH];
#pragma unroll
        for (int j = 0; j < NH; j++) v[j] = __shfl_sync(0xffffffffu, h, j, 16);
        float a0 = fmaf(v[0], wrow[0], p + bias);
        float a1 = v[1] * wrow[1];
        float a2 = v[2] * wrow[2];
#pragma unroll
        for (int j = 3; j < NH; j += 3) {
            a0 = fmaf(v[j    ], wrow[j    ], a0);
            a1 = fmaf(v[j + 1], wrow[j + 1], a1);
            a2 = fmaf(v[j + 2], wrow[j + 2], a2);
        }
        h = ftanh(a0 + a1 + a2);
    }

    float v[NH];
#pragma unroll
    for (int j = 0; j < NH; j++) v[j] = __shfl_sync(0xffffffffu, h, j, 16);
    if (hl < NOUT) {
        float o = fcb[hl];
        const float* hb = g_hbwd + (size_t)b * NH;
#pragma unroll
        for (int j = 0; j < NH; j++) o = fmaf(v[j], fcw[hl * 2 * NH + j], o);
#pragma unroll
        for (int j = 0; j < NH; j++) o = fmaf(hb[j], fcw[hl * 2 * NH + NH + j], o);
        out[b * NOUT + hl] = o;
    }
}

// ---------------------------------------------------------------------------
extern "C" void kernel_launch(void* const* d_in, const int* in_sizes, int n_in,
                              void* d_out, int out_size) {
    const int*   x      = (const int*)  d_in[0];
    const float* emb    = (const float*)d_in[1];
    const float* w_ih_f = (const float*)d_in[2];
    const float* w_hh_f = (const float*)d_in[3];
    const float* b_ih_f = (const float*)d_in[4];
    const float* b_hh_f = (const float*)d_in[5];
    const float* w_ih_r = (const float*)d_in[6];
    // d_in[7] = w_hh_r (unused: reference consumes only the one-step reverse state)
    const float* b_ih_r = (const float*)d_in[8];
    const float* b_hh_r = (const float*)d_in[9];
    const float* fc_w   = (const float*)d_in[10];
    const float* fc_b   = (const float*)d_in[11];
    float* out = (float*)d_out;

    const int smem = INS * SCH * 4 + INS * 6 * 8 + BPB * INS * 4;  // 106496 B
    cudaFuncSetAttribute(pre_kernel, cudaFuncAttributeMaxDynamicSharedMemorySize, smem);

    pre_kernel<<<dim3(NB / BPB, SEQL / SCH), 256, smem>>>(x, emb, w_ih_f);
    bwd_kernel<<<NB / 8, 256>>>(x, emb, w_ih_r, b_ih_r, b_hh_r);
    scan_kernel<<<NB / 16, 256>>>(w_hh_f, b_ih_f, b_hh_f, fc_w, fc_b, out);
}

// round 4
// speedup vs baseline: 1.5536x; 1.5536x over previous
#include <cuda_runtime.h>
#include <cstdint>

#define NB   2048
#define INS  512
#define SEQL 128
#define NH   12
#define NOUT 3
#define BPB  4   // batches per block in pre_kernel (1 warp per batch)

// scratch (allocation-free contract: __device__ globals)
__device__ float g_pre[(size_t)SEQL * NB * NH];   // [s][b][h]  ~12.6 MB
__device__ float g_hbwd[NB * NH];

__device__ __forceinline__ unsigned long long fma2(unsigned long long a,
                                                   unsigned long long b,
                                                   unsigned long long c) {
    unsigned long long d;
    asm("fma.rn.f32x2 %0, %1, %2, %3;" : "=l"(d) : "l"(a), "l"(b), "l"(c));
    return d;
}
__device__ __forceinline__ unsigned long long pk2(float f) {
    unsigned long long u;
    asm("mov.b64 %0, {%1, %1};" : "=l"(u) : "f"(f));
    return u;
}
__device__ __forceinline__ float ftanh(float x) {
    float e = __expf(2.0f * x);
    return 1.0f - __fdividef(2.0f, e + 1.0f);
}

// ---------------------------------------------------------------------------
// Kernel 1: pre[s,b,h] = sum_i emb[x[b,i], s] * w_ih_f[h,i]
// grid (NB/BPB, 2); warp per batch; lane owns s0 = 64*y + 2*lane, s1 = s0+1.
// e gathered via LDG.64 from L2-resident emb, software-pipelined 8-deep with
// ping-pong register buffers (MLP=8) to hide the ~250cyc L2 latency that held
// R1/R2 at issue=35%. Weights as float2 pairs in smem: 3 broadcast LDS.128/i.
// 12 fma.rn.f32x2 per i per lane (6 per s).
// ---------------------------------------------------------------------------
extern "C" __global__ void __launch_bounds__(128)
pre_kernel(const int* __restrict__ x, const float* __restrict__ emb,
           const float* __restrict__ wih) {
    __shared__ float2 w2[INS * 6];   // 24 KB: w2[i*6+k] = (w[2k,i], w[2k+1,i])
    __shared__ int    xs[BPB * INS]; // 8 KB

    const int tid = threadIdx.x;
    const int b0 = blockIdx.x * BPB;

    for (int t = tid; t < INS * 6; t += 128) {
        int i = t & (INS - 1);
        int k = t >> 9;              // 0..5
        w2[i * 6 + k] = make_float2(wih[(2 * k) * INS + i],
                                    wih[(2 * k + 1) * INS + i]);
    }
    for (int t = tid; t < BPB * INS; t += 128)
        xs[t] = x[(size_t)b0 * INS + t];
    __syncthreads();

    const int warp = tid >> 5;
    const int lane = tid & 31;
    const int b = b0 + warp;
    const int sbase = blockIdx.y * 64 + lane * 2;
    const int* xrow = xs + warp * INS;
    const float* ebase = emb + sbase;

    unsigned long long a0[6], a1[6];   // s0 / s1 accumulators, h-pairs
#pragma unroll
    for (int k = 0; k < 6; k++) { a0[k] = 0ull; a1[k] = 0ull; }

    float2 eA[8], eB[8];

#define LOADE(buf, base_i)                                                    \
    do {                                                                      \
        int4 qa = *(const int4*)(xrow + (base_i));                            \
        int4 qb = *(const int4*)(xrow + (base_i) + 4);                        \
        buf[0] = *(const float2*)(ebase + (size_t)qa.x * SEQL);              \
        buf[1] = *(const float2*)(ebase + (size_t)qa.y * SEQL);              \
        buf[2] = *(const float2*)(ebase + (size_t)qa.z * SEQL);              \
        buf[3] = *(const float2*)(ebase + (size_t)qa.w * SEQL);              \
        buf[4] = *(const float2*)(ebase + (size_t)qb.x * SEQL);              \
        buf[5] = *(const float2*)(ebase + (size_t)qb.y * SEQL);              \
        buf[6] = *(const float2*)(ebase + (size_t)qb.z * SEQL);              \
        buf[7] = *(const float2*)(ebase + (size_t)qb.w * SEQL);              \
    } while (0)

#define COMPUTE8(buf, base_i)                                                 \
    do {                                                                      \
        _Pragma("unroll")                                                     \
        for (int u = 0; u < 8; u++) {                                         \
            unsigned long long p0 = pk2(buf[u].x);                            \
            unsigned long long p1 = pk2(buf[u].y);                            \
            const ulonglong2* wv =                                            \
                (const ulonglong2*)(w2 + (size_t)((base_i) + u) * 6);         \
            ulonglong2 wA = wv[0], wB = wv[1], wC = wv[2];                    \
            a0[0] = fma2(p0, wA.x, a0[0]);                                    \
            a1[0] = fma2(p1, wA.x, a1[0]);                                    \
            a0[1] = fma2(p0, wA.y, a0[1]);                                    \
            a1[1] = fma2(p1, wA.y, a1[1]);                                    \
            a0[2] = fma2(p0, wB.x, a0[2]);                                    \
            a1[2] = fma2(p1, wB.x, a1[2]);                                    \
            a0[3] = fma2(p0, wB.y, a0[3]);                                    \
            a1[3] = fma2(p1, wB.y, a1[3]);                                    \
            a0[4] = fma2(p0, wC.x, a0[4]);                                    \
            a1[4] = fma2(p1, wC.x, a1[4]);                                    \
            a0[5] = fma2(p0, wC.y, a0[5]);                                    \
            a1[5] = fma2(p1, wC.y, a1[5]);                                    \
        }                                                                     \
    } while (0)

    LOADE(eA, 0);

#pragma unroll 1
    for (int i0 = 0; i0 < INS; i0 += 16) {
        LOADE(eB, i0 + 8);                     // loads for second half in flight
        COMPUTE8(eA, i0);                      // compute first half
        LOADE(eA, (i0 + 16 < INS) ? (i0 + 16) : 0);  // next chunk (tail clamp)
        COMPUTE8(eB, i0 + 8);                  // compute second half
    }
#undef LOADE
#undef COMPUTE8

    // a0[k] = (pre[s0,b,2k], pre[s0,b,2k+1]); a1 likewise for s1 = s0+1
    {
        ulonglong2* d = (ulonglong2*)(g_pre + ((size_t)sbase * NB + b) * NH);
        ulonglong2 v0, v1, v2;
        v0.x = a0[0]; v0.y = a0[1];
        v1.x = a0[2]; v1.y = a0[3];
        v2.x = a0[4]; v2.y = a0[5];
        d[0] = v0; d[1] = v1; d[2] = v2;
    }
    {
        ulonglong2* d =
            (ulonglong2*)(g_pre + ((size_t)(sbase + 1) * NB + b) * NH);
        ulonglong2 v0, v1, v2;
        v0.x = a1[0]; v0.y = a1[1];
        v1.x = a1[2]; v1.y = a1[3];
        v2.x = a1[4]; v2.y = a1[5];
        d[0] = v0; d[1] = v1; d[2] = v2;
    }
}

// ---------------------------------------------------------------------------
// Kernel 2: h_bwd — warp per batch, MLP=16 prefetch.
// ---------------------------------------------------------------------------
extern "C" __global__ void __launch_bounds__(256)
bwd_kernel(const int* __restrict__ x, const float* __restrict__ emb,
           const float* __restrict__ wir, const float* __restrict__ bir,
           const float* __restrict__ bhr) {
    __shared__ float ws[NH * INS];   // 24 KB
    const int tid = threadIdx.x;
    for (int t = tid; t < NH * INS; t += 256) ws[t] = wir[t];
    __syncthreads();

    const int warp = tid >> 5, lane = tid & 31;
    const int b = blockIdx.x * 8 + warp;

    int idxv[16];
#pragma unroll
    for (int j = 0; j < 16; j++)
        idxv[j] = x[(size_t)b * INS + lane + 32 * j];
    float ev[16];
#pragma unroll
    for (int j = 0; j < 16; j++)
        ev[j] = emb[(size_t)idxv[j] * SEQL + (SEQL - 1)];

    float p[NH];
#pragma unroll
    for (int h = 0; h < NH; h++) p[h] = 0.f;
#pragma unroll
    for (int j = 0; j < 16; j++) {
        const int i = lane + 32 * j;
#pragma unroll
        for (int h = 0; h < NH; h++) p[h] = fmaf(ev[j], ws[h * INS + i], p[h]);
    }
#pragma unroll
    for (int h = 0; h < NH; h++) {
        float v = p[h];
#pragma unroll
        for (int o = 16; o; o >>= 1) v += __shfl_xor_sync(0xffffffffu, v, o);
        p[h] = v;
    }
    if (lane == 0) {
        float r[NH];
#pragma unroll
        for (int h = 0; h < NH; h++) r[h] = ftanh(p[h] + bir[h] + bhr[h]);
        float4* d = (float4*)(g_hbwd + (size_t)b * NH);
        d[0] = make_float4(r[0], r[1], r[2], r[3]);
        d[1] = make_float4(r[4], r[5], r[6], r[7]);
        d[2] = make_float4(r[8], r[9], r[10], r[11]);
    }
}

// ---------------------------------------------------------------------------
// Kernel 3: forward scan + fused FC epilogue.
// ---------------------------------------------------------------------------
extern "C" __global__ void __launch_bounds__(256)
scan_kernel(const float* __restrict__ whh, const float* __restrict__ bih,
            const float* __restrict__ bhh, const float* __restrict__ fcw,
            const float* __restrict__ fcb, float* __restrict__ out) {
    const int tid = threadIdx.x;
    const int b = blockIdx.x * 16 + (tid >> 4);
    const int hl = tid & 15;
    const int hc = hl < NH ? hl : 0;

    float wrow[NH];
#pragma unroll
    for (int j = 0; j < NH; j++) wrow[j] = whh[hc * NH + j];
    const float bias = bih[hc] + bhh[hc];

    const float* ps = g_pre + (size_t)b * NH + hc;
    float h = 0.f;
    float pnext = ps[0];

    for (int s = 0; s < SEQL; s++) {
        float p = pnext;
        if (s + 1 < SEQL) pnext = ps[(size_t)(s + 1) * NB * NH];
        float v[NH];
#pragma unroll
        for (int j = 0; j < NH; j++) v[j] = __shfl_sync(0xffffffffu, h, j, 16);
        float t0 = fmaf(v[0], wrow[0], p + bias);
        float t1 = v[1] * wrow[1];
        float t2 = v[2] * wrow[2];
#pragma unroll
        for (int j = 3; j < NH; j += 3) {
            t0 = fmaf(v[j    ], wrow[j    ], t0);
            t1 = fmaf(v[j + 1], wrow[j + 1], t1);
            t2 = fmaf(v[j + 2], wrow[j + 2], t2);
        }
        h = ftanh(t0 + t1 + t2);
    }

    float v[NH];
#pragma unroll
    for (int j = 0; j < NH; j++) v[j] = __shfl_sync(0xffffffffu, h, j, 16);
    if (hl < NOUT) {
        float o = fcb[hl];
        const float* hb = g_hbwd + (size_t)b * NH;
#pragma unroll
        for (int j = 0; j < NH; j++) o = fmaf(v[j], fcw[hl * 2 * NH + j], o);
#pragma unroll
        for (int j = 0; j < NH; j++) o = fmaf(hb[j], fcw[hl * 2 * NH + NH + j], o);
        out[b * NOUT + hl] = o;
    }
}

// ---------------------------------------------------------------------------
extern "C" void kernel_launch(void* const* d_in, const int* in_sizes, int n_in,
                              void* d_out, int out_size) {
    const int*   x      = (const int*)  d_in[0];
    const float* emb    = (const float*)d_in[1];
    const float* w_ih_f = (const float*)d_in[2];
    const float* w_hh_f = (const float*)d_in[3];
    const float* b_ih_f = (const float*)d_in[4];
    const float* b_hh_f = (const float*)d_in[5];
    const float* w_ih_r = (const float*)d_in[6];
    // d_in[7] = w_hh_r (unused: reference consumes only the one-step reverse state)
    const float* b_ih_r = (const float*)d_in[8];
    const float* b_hh_r = (const float*)d_in[9];
    const float* fc_w   = (const float*)d_in[10];
    const float* fc_b   = (const float*)d_in[11];
    float* out = (float*)d_out;

    pre_kernel<<<dim3(NB / BPB, 2), 128>>>(x, emb, w_ih_f);
    bwd_kernel<<<NB / 8, 256>>>(x, emb, w_ih_r, b_ih_r, b_hh_r);
    scan_kernel<<<NB / 16, 256>>>(w_hh_f, b_ih_f, b_hh_f, fc_w, fc_b, out);
}